// round 5
// baseline (speedup 1.0000x reference)
#include <cuda_runtime.h>
#include <cstdint>

// XSimGCL / LightGCN propagation on GB300 (sm_103a).
// final = mean(X1,X2,X3), Xk = A_hat @ X(k-1); out[b] = dot(final[u_b], final[i_b + NU]).
// Structure: output needs `final` at <=8192 rows -> layer 3 is bitmap-predicated.
//
// Scratch __device__ globals are ONLY referenced from device code (host code
// sees shadow symbols with wrong addresses -> that was the R1 bug).

#define NUM_USERS 100000
#define NUM_ITEMS 50000
#define NTOT      (NUM_USERS + NUM_ITEMS)   // 150000
#define D4        16                        // float4s per 64-dim row
#define BATCH     4096

__device__ float4 g_X0[NTOT * D4];
__device__ float4 g_X1[NTOT * D4];
__device__ float4 g_X2[NTOT * D4];
__device__ float4 g_X3[NTOT * D4];
__device__ unsigned g_bitmap[(NTOT + 31) / 32];

// ---------------------------------------------------------------------------
// Init: X0 = concat(user_emb, item_emb); zero X1/X2/X3 and bitmap.
// ---------------------------------------------------------------------------
__global__ void init_kernel(const float4* __restrict__ ue,
                            const float4* __restrict__ ie) {
    int i = blockIdx.x * blockDim.x + threadIdx.x;
    const float4 z = make_float4(0.f, 0.f, 0.f, 0.f);
    if (i < NTOT * D4) {
        g_X0[i] = (i < NUM_USERS * D4) ? ue[i] : ie[i - NUM_USERS * D4];
        g_X1[i] = z;
        g_X2[i] = z;
        g_X3[i] = z;
    }
    if (i < (NTOT + 31) / 32) g_bitmap[i] = 0u;
}

// Mark rows whose layer-3 output is actually needed.
__global__ void mark_kernel(const int* __restrict__ uid,
                            const int* __restrict__ iid) {
    int i = blockIdx.x * blockDim.x + threadIdx.x;
    if (i < BATCH) {
        unsigned r = (unsigned)uid[i];
        if (r < NUM_USERS)
            atomicOr(&g_bitmap[r >> 5], 1u << (r & 31));
        unsigned r2 = (unsigned)iid[i] + NUM_USERS;
        if (r2 < NTOT)
            atomicOr(&g_bitmap[r2 >> 5], 1u << (r2 & 31));
    }
}

// ---------------------------------------------------------------------------
// COO SpMM: Y[rows[e]] += vals[e] * X[cols[e]].  16 threads/edge, 1 float4 each.
//   gather  = one contiguous 256B line per edge (L2-resident working set)
//   scatter = one contiguous 256B red.global.add.v4.f32 burst per edge
// LAYER selects src/dst scratch buffers IN DEVICE CODE (legal global refs).
// PRED=true: skip edges whose destination row isn't flagged (layer 3).
// ---------------------------------------------------------------------------
template <bool PRED, int LAYER>
__global__ void __launch_bounds__(256)
spmm_kernel(const float* __restrict__ vals,
            const int*   __restrict__ rows,
            const int*   __restrict__ cols,
            int ne) {
    const float4* __restrict__ X = (LAYER == 0) ? g_X0 : (LAYER == 1) ? g_X1 : g_X2;
    float4* __restrict__       Y = (LAYER == 0) ? g_X1 : (LAYER == 1) ? g_X2 : g_X3;

    int gid = blockIdx.x * blockDim.x + threadIdx.x;
    int e = gid >> 4;
    int l = gid & 15;
    if (e >= ne) return;

    unsigned r = (unsigned)__ldg(&rows[e]);
    if (r >= NTOT) return;                       // defensive: finite wrong > trap
    if (PRED) {
        if (!((g_bitmap[r >> 5] >> (r & 31)) & 1u)) return;
    }
    unsigned c = (unsigned)__ldg(&cols[e]);
    if (c >= NTOT) return;
    float v = __ldg(&vals[e]);

    float4 x = __ldg(&X[c * D4 + l]);
    float4 s = make_float4(v * x.x, v * x.y, v * x.z, v * x.w);

    float* p = reinterpret_cast<float*>(&Y[r * D4 + l]);
    asm volatile("red.global.add.v4.f32 [%0], {%1, %2, %3, %4};"
                 :: "l"(p), "f"(s.x), "f"(s.y), "f"(s.z), "f"(s.w)
                 : "memory");
}

// ---------------------------------------------------------------------------
// Readout: out[b] = dot((X1+X2+X3)[u], (X1+X2+X3)[i+NU]) / 9
// 16 threads per batch element; shfl-reduce within the 16-lane group.
// ---------------------------------------------------------------------------
__global__ void dot_kernel(const int* __restrict__ uid,
                           const int* __restrict__ iid,
                           float* __restrict__ out) {
    int gid = blockIdx.x * blockDim.x + threadIdx.x;
    int b = gid >> 4;
    int l = gid & 15;
    if (b >= BATCH) return;

    unsigned ur = (unsigned)__ldg(&uid[b]);
    unsigned ir = (unsigned)__ldg(&iid[b]) + NUM_USERS;
    float d = 0.f;

    if (ur < NTOT && ir < NTOT) {
        int uo = (int)ur * D4 + l;
        int io = (int)ir * D4 + l;

        float4 a1 = g_X1[uo], a2 = g_X2[uo], a3 = g_X3[uo];
        float4 b1 = g_X1[io], b2 = g_X2[io], b3 = g_X3[io];

        float fux = a1.x + a2.x + a3.x, fuy = a1.y + a2.y + a3.y;
        float fuz = a1.z + a2.z + a3.z, fuw = a1.w + a2.w + a3.w;
        float fix = b1.x + b2.x + b3.x, fiy = b1.y + b2.y + b3.y;
        float fiz = b1.z + b2.z + b3.z, fiw = b1.w + b2.w + b3.w;

        d = fux * fix + fuy * fiy + fuz * fiz + fuw * fiw;
    }

    #pragma unroll
    for (int off = 8; off > 0; off >>= 1)
        d += __shfl_down_sync(0xffffffffu, d, off, 16);

    if (l == 0) out[b] = d * (1.0f / 9.0f);   // /3 per side of the dot
}

// ---------------------------------------------------------------------------
extern "C" void kernel_launch(void* const* d_in, const int* in_sizes, int n_in,
                              void* d_out, int out_size) {
    const float4* user_emb = (const float4*)d_in[0];   // [100000,64] f32
    const float4* item_emb = (const float4*)d_in[1];   // [50000,64]  f32
    const float*  vals     = (const float*) d_in[2];   // [2E] f32
    const int*    rows     = (const int*)   d_in[3];   // [2E] i32
    const int*    cols     = (const int*)   d_in[4];   // [2E] i32
    const int*    uid      = (const int*)   d_in[5];   // [4096] i32
    const int*    iid      = (const int*)   d_in[6];   // [4096] i32
    float*        out      = (float*)d_out;            // [4096] f32

    const int ne = in_sizes[2];

    {
        int n = NTOT * D4;
        init_kernel<<<(n + 255) / 256, 256>>>(user_emb, item_emb);
        mark_kernel<<<(BATCH + 255) / 256, 256>>>(uid, iid);
    }

    {
        long long threads = (long long)ne * 16;        // 64M for ne=4M
        int blocks = (int)((threads + 255) / 256);
        spmm_kernel<false, 0><<<blocks, 256>>>(vals, rows, cols, ne);
        spmm_kernel<false, 1><<<blocks, 256>>>(vals, rows, cols, ne);
        spmm_kernel<true,  2><<<blocks, 256>>>(vals, rows, cols, ne);
    }

    {
        int threads = BATCH * 16;
        dot_kernel<<<(threads + 255) / 256, 256>>>(uid, iid, out);
    }
}

// round 6
// speedup vs baseline: 1.8003x; 1.8003x over previous
#include <cuda_runtime.h>
#include <cstdint>

// XSimGCL / LightGCN on GB300 (sm_103a) — CSR formulation, zero float atomics.
// R5 post-mortem: 64M RED.128 lanes/layer bound the dense layers (~1.3 cyc/lane).
// Now: on-device counting-sort -> CSR, then SpMM = gather + register acc + 1 store/row.

#define NUM_USERS 100000
#define NUM_ITEMS 50000
#define NTOT      (NUM_USERS + NUM_ITEMS)   // 150000
#define D4        16                        // float4s per 64-dim row
#define BATCH     4096
#define MAXE      4200000                   // >= 2*NUM_BASE_EDGES
#define MAXROWS   8192                      // <= 2*BATCH unique flagged rows

// Scratch (allocation-free rule: __device__ globals; referenced ONLY in device code).
__device__ float4   g_X1[NTOT * D4];
__device__ float4   g_X2[NTOT * D4];
__device__ float4   g_X3[NTOT * D4];
__device__ int      g_cnt[NTOT];
__device__ int      g_off[NTOT + 1];
__device__ int      g_pos[NTOT];
__device__ int2     g_cva[MAXE];            // packed {col, float_as_int(val)}
__device__ unsigned g_bitmap[(NTOT + 31) / 32];
__device__ int      g_rowlist[MAXROWS];
__device__ int      g_nrows;

// ---------------------------------------------------------------------------
// Zero the per-call build state (histogram, bitmap, row counter).
// ---------------------------------------------------------------------------
__global__ void zero_kernel() {
    int i = blockIdx.x * blockDim.x + threadIdx.x;
    if (i < NTOT) g_cnt[i] = 0;
    if (i < (NTOT + 31) / 32) g_bitmap[i] = 0u;
    if (i == 0) g_nrows = 0;
}

// Mark rows whose layer-3 output is needed; compact unique rows into g_rowlist.
__global__ void mark_kernel(const int* __restrict__ uid,
                            const int* __restrict__ iid) {
    int i = blockIdx.x * blockDim.x + threadIdx.x;
    if (i >= BATCH) return;
    unsigned r[2];
    r[0] = (unsigned)uid[i];
    r[1] = (unsigned)iid[i] + NUM_USERS;
    #pragma unroll
    for (int k = 0; k < 2; k++) {
        if (r[k] < NTOT) {
            unsigned bit = 1u << (r[k] & 31);
            unsigned old = atomicOr(&g_bitmap[r[k] >> 5], bit);
            if (!(old & bit)) {
                int p = atomicAdd(&g_nrows, 1);
                if (p < MAXROWS) g_rowlist[p] = (int)r[k];
            }
        }
    }
}

// ---------------------------------------------------------------------------
// CSR build: degree histogram -> single-block scan -> scatter packed edges.
// ---------------------------------------------------------------------------
__global__ void degree_kernel(const int* __restrict__ rows, int ne) {
    int e = blockIdx.x * blockDim.x + threadIdx.x;
    if (e >= ne) return;
    unsigned r = (unsigned)__ldg(&rows[e]);
    if (r < NTOT) atomicAdd(&g_cnt[r], 1);
}

__global__ void scan_kernel() {   // 1 block, 1024 threads
    const int T = 1024;
    const int CH = (NTOT + T - 1) / T;      // 147
    int tid = threadIdx.x;
    int base = tid * CH;

    int s = 0;
    for (int i = 0; i < CH; i++) {
        int idx = base + i;
        if (idx < NTOT) s += g_cnt[idx];
    }
    __shared__ int sh[T];
    sh[tid] = s;
    __syncthreads();
    // Hillis-Steele inclusive scan
    for (int off = 1; off < T; off <<= 1) {
        int v = (tid >= off) ? sh[tid - off] : 0;
        __syncthreads();
        sh[tid] += v;
        __syncthreads();
    }
    int run = sh[tid] - s;                  // exclusive prefix for this chunk
    for (int i = 0; i < CH; i++) {
        int idx = base + i;
        if (idx < NTOT) {
            int c = g_cnt[idx];
            g_off[idx] = run;
            g_pos[idx] = run;
            run += c;
        }
    }
    if (tid == T - 1) g_off[NTOT] = run;
}

__global__ void scatter_kernel(const float* __restrict__ vals,
                               const int*   __restrict__ rows,
                               const int*   __restrict__ cols,
                               int ne) {
    int e = blockIdx.x * blockDim.x + threadIdx.x;
    if (e >= ne) return;
    unsigned r = (unsigned)__ldg(&rows[e]);
    if (r >= NTOT) return;
    int c = __ldg(&cols[e]);
    float v = __ldg(&vals[e]);
    int p = atomicAdd(&g_pos[r], 1);
    if (p < MAXE) g_cva[p] = make_int2(c, __float_as_int(v));
}

// ---------------------------------------------------------------------------
// CSR SpMM: one 16-lane group per row, register accumulate, single store.
// LAYER 0: src = (user_emb|item_emb) direct, dst = X1
// LAYER 1: X1 -> X2
// LAYER 2: X2 -> X3, only over compacted g_rowlist (<= g_nrows rows)
// ---------------------------------------------------------------------------
template <int LAYER>
__global__ void __launch_bounds__(256)
spmm_csr_kernel(const float4* __restrict__ ue,
                const float4* __restrict__ ie) {
    int gid = blockIdx.x * blockDim.x + threadIdx.x;
    int g = gid >> 4;
    int l = gid & 15;

    int r;
    if (LAYER == 2) {
        if (g >= g_nrows) return;
        r = g_rowlist[g];
    } else {
        if (g >= NTOT) return;
        r = g;
    }

    int beg = __ldg(&g_off[r]);
    int end = __ldg(&g_off[r + 1]);

    const float4* __restrict__ src = (LAYER == 1) ? g_X1 : g_X2;  // unused for LAYER 0
    float4 acc = make_float4(0.f, 0.f, 0.f, 0.f);

    int j = beg;
    for (; j + 1 < end; j += 2) {       // issue both gathers before consuming
        int2 ca = __ldg(&g_cva[j]);
        int2 cb = __ldg(&g_cva[j + 1]);
        float4 xa, xb;
        if (LAYER == 0) {
            xa = (ca.x < NUM_USERS) ? __ldg(&ue[ca.x * D4 + l])
                                    : __ldg(&ie[(ca.x - NUM_USERS) * D4 + l]);
            xb = (cb.x < NUM_USERS) ? __ldg(&ue[cb.x * D4 + l])
                                    : __ldg(&ie[(cb.x - NUM_USERS) * D4 + l]);
        } else {
            xa = __ldg(&src[ca.x * D4 + l]);
            xb = __ldg(&src[cb.x * D4 + l]);
        }
        float va = __int_as_float(ca.y), vb = __int_as_float(cb.y);
        acc.x += va * xa.x + vb * xb.x;
        acc.y += va * xa.y + vb * xb.y;
        acc.z += va * xa.z + vb * xb.z;
        acc.w += va * xa.w + vb * xb.w;
    }
    if (j < end) {
        int2 ca = __ldg(&g_cva[j]);
        float4 xa;
        if (LAYER == 0) {
            xa = (ca.x < NUM_USERS) ? __ldg(&ue[ca.x * D4 + l])
                                    : __ldg(&ie[(ca.x - NUM_USERS) * D4 + l]);
        } else {
            xa = __ldg(&src[ca.x * D4 + l]);
        }
        float va = __int_as_float(ca.y);
        acc.x += va * xa.x; acc.y += va * xa.y;
        acc.z += va * xa.z; acc.w += va * xa.w;
    }

    float4* __restrict__ dst = (LAYER == 0) ? g_X1 : (LAYER == 1) ? g_X2 : g_X3;
    dst[r * D4 + l] = acc;
}

// ---------------------------------------------------------------------------
// Readout: out[b] = dot((X1+X2+X3)[u], (X1+X2+X3)[i+NU]) / 9
// ---------------------------------------------------------------------------
__global__ void dot_kernel(const int* __restrict__ uid,
                           const int* __restrict__ iid,
                           float* __restrict__ out) {
    int gid = blockIdx.x * blockDim.x + threadIdx.x;
    int b = gid >> 4;
    int l = gid & 15;
    if (b >= BATCH) return;

    unsigned ur = (unsigned)__ldg(&uid[b]);
    unsigned ir = (unsigned)__ldg(&iid[b]) + NUM_USERS;
    float d = 0.f;

    if (ur < NTOT && ir < NTOT) {
        int uo = (int)ur * D4 + l;
        int io = (int)ir * D4 + l;
        float4 a1 = g_X1[uo], a2 = g_X2[uo], a3 = g_X3[uo];
        float4 b1 = g_X1[io], b2 = g_X2[io], b3 = g_X3[io];
        float fux = a1.x + a2.x + a3.x, fuy = a1.y + a2.y + a3.y;
        float fuz = a1.z + a2.z + a3.z, fuw = a1.w + a2.w + a3.w;
        float fix = b1.x + b2.x + b3.x, fiy = b1.y + b2.y + b3.y;
        float fiz = b1.z + b2.z + b3.z, fiw = b1.w + b2.w + b3.w;
        d = fux * fix + fuy * fiy + fuz * fiz + fuw * fiw;
    }

    #pragma unroll
    for (int off = 8; off > 0; off >>= 1)
        d += __shfl_down_sync(0xffffffffu, d, off, 16);

    if (l == 0) out[b] = d * (1.0f / 9.0f);
}

// ---------------------------------------------------------------------------
extern "C" void kernel_launch(void* const* d_in, const int* in_sizes, int n_in,
                              void* d_out, int out_size) {
    const float4* user_emb = (const float4*)d_in[0];   // [100000,64] f32
    const float4* item_emb = (const float4*)d_in[1];   // [50000,64]  f32
    const float*  vals     = (const float*) d_in[2];   // [2E] f32
    const int*    rows     = (const int*)   d_in[3];   // [2E] i32
    const int*    cols     = (const int*)   d_in[4];   // [2E] i32
    const int*    uid      = (const int*)   d_in[5];   // [4096] i32
    const int*    iid      = (const int*)   d_in[6];   // [4096] i32
    float*        out      = (float*)d_out;            // [4096] f32

    const int ne = in_sizes[2];

    // build state + flagged-row compaction
    zero_kernel<<<(NTOT + 255) / 256, 256>>>();
    mark_kernel<<<(BATCH + 255) / 256, 256>>>(uid, iid);

    // CSR build (counting sort)
    int eblocks = (ne + 255) / 256;
    degree_kernel<<<eblocks, 256>>>(rows, ne);
    scan_kernel<<<1, 1024>>>();
    scatter_kernel<<<eblocks, 256>>>(vals, rows, cols, ne);

    // 3 propagation layers (layer 3 over compacted row list only)
    {
        int t_dense = NTOT * D4;
        spmm_csr_kernel<0><<<(t_dense + 255) / 256, 256>>>(user_emb, item_emb);
        spmm_csr_kernel<1><<<(t_dense + 255) / 256, 256>>>(user_emb, item_emb);
        int t_sparse = MAXROWS * 16;
        spmm_csr_kernel<2><<<(t_sparse + 255) / 256, 256>>>(user_emb, item_emb);
    }

    dot_kernel<<<(BATCH * 16 + 255) / 256, 256>>>(uid, iid, out);
}

// round 7
// speedup vs baseline: 3.2025x; 1.7788x over previous
#include <cuda_runtime.h>
#include <cstdint>

// XSimGCL / LightGCN on GB300 (sm_103a) — CSR formulation, zero float atomics.
// R6 post-mortem: single-block scan_kernel was 238us (47% of total). Replaced
// with a 3-pass parallel scan (block reduce -> scan partials -> block rescan).

#define NUM_USERS 100000
#define NUM_ITEMS 50000
#define NTOT      (NUM_USERS + NUM_ITEMS)   // 150000
#define D4        16                        // float4s per 64-dim row
#define BATCH     4096
#define MAXE      4200000                   // >= 2*NUM_BASE_EDGES
#define MAXROWS   8192                      // <= 2*BATCH unique flagged rows
#define SCAN_B    256
#define NBLK      ((NTOT + SCAN_B - 1) / SCAN_B)   // 586

// Scratch (allocation-free rule: __device__ globals; device-code refs only).
__device__ float4   g_X1[NTOT * D4];
__device__ float4   g_X2[NTOT * D4];
__device__ float4   g_X3[NTOT * D4];
__device__ int      g_cnt[NTOT];
__device__ int      g_off[NTOT + 1];
__device__ int      g_pos[NTOT];
__device__ int      g_part[1024];           // >= NBLK
__device__ int2     g_cva[MAXE];            // packed {col, float_as_int(val)}
__device__ unsigned g_bitmap[(NTOT + 31) / 32];
__device__ int      g_rowlist[MAXROWS];
__device__ int      g_nrows;

// ---------------------------------------------------------------------------
__global__ void zero_kernel() {
    int i = blockIdx.x * blockDim.x + threadIdx.x;
    if (i < NTOT) g_cnt[i] = 0;
    if (i < (NTOT + 31) / 32) g_bitmap[i] = 0u;
    if (i == 0) g_nrows = 0;
}

// Mark rows whose layer-3 output is needed; compact unique rows into g_rowlist.
__global__ void mark_kernel(const int* __restrict__ uid,
                            const int* __restrict__ iid) {
    int i = blockIdx.x * blockDim.x + threadIdx.x;
    if (i >= BATCH) return;
    unsigned r[2];
    r[0] = (unsigned)uid[i];
    r[1] = (unsigned)iid[i] + NUM_USERS;
    #pragma unroll
    for (int k = 0; k < 2; k++) {
        if (r[k] < NTOT) {
            unsigned bit = 1u << (r[k] & 31);
            unsigned old = atomicOr(&g_bitmap[r[k] >> 5], bit);
            if (!(old & bit)) {
                int p = atomicAdd(&g_nrows, 1);
                if (p < MAXROWS) g_rowlist[p] = (int)r[k];
            }
        }
    }
}

// ---------------------------------------------------------------------------
// CSR build: histogram -> 3-pass parallel exclusive scan -> scatter.
// ---------------------------------------------------------------------------
__global__ void degree_kernel(const int* __restrict__ rows, int ne) {
    int e = blockIdx.x * blockDim.x + threadIdx.x;
    if (e >= ne) return;
    unsigned r = (unsigned)__ldg(&rows[e]);
    if (r < NTOT) atomicAdd(&g_cnt[r], 1);
}

// Pass A: per-block sum of a 256-element chunk of g_cnt.
__global__ void scan_reduce_kernel() {
    __shared__ int sh[SCAN_B];
    int idx = blockIdx.x * SCAN_B + threadIdx.x;
    sh[threadIdx.x] = (idx < NTOT) ? g_cnt[idx] : 0;
    __syncthreads();
    #pragma unroll
    for (int off = SCAN_B / 2; off > 0; off >>= 1) {
        if (threadIdx.x < off) sh[threadIdx.x] += sh[threadIdx.x + off];
        __syncthreads();
    }
    if (threadIdx.x == 0) g_part[blockIdx.x] = sh[0];
}

// Pass B: single small block scans the NBLK partials (exclusive).
__global__ void scan_partials_kernel() {
    __shared__ int sh[1024];
    int tid = threadIdx.x;
    int v = (tid < NBLK) ? g_part[tid] : 0;
    sh[tid] = v;
    __syncthreads();
    for (int off = 1; off < 1024; off <<= 1) {
        int t = (tid >= off) ? sh[tid - off] : 0;
        __syncthreads();
        sh[tid] += t;
        __syncthreads();
    }
    if (tid < NBLK) g_part[tid] = sh[tid] - v;   // exclusive
    if (tid == NBLK - 1) g_off[NTOT] = sh[tid];  // total edge count
}

// Pass C: intra-block exclusive scan + partial base -> g_off / g_pos.
__global__ void scan_final_kernel() {
    __shared__ int sh[SCAN_B];
    int idx = blockIdx.x * SCAN_B + threadIdx.x;
    int c = (idx < NTOT) ? g_cnt[idx] : 0;
    sh[threadIdx.x] = c;
    __syncthreads();
    #pragma unroll
    for (int off = 1; off < SCAN_B; off <<= 1) {
        int t = (threadIdx.x >= off) ? sh[threadIdx.x - off] : 0;
        __syncthreads();
        sh[threadIdx.x] += t;
        __syncthreads();
    }
    if (idx < NTOT) {
        int off = g_part[blockIdx.x] + sh[threadIdx.x] - c;   // exclusive
        g_off[idx] = off;
        g_pos[idx] = off;
    }
}

__global__ void scatter_kernel(const float* __restrict__ vals,
                               const int*   __restrict__ rows,
                               const int*   __restrict__ cols,
                               int ne) {
    int e = blockIdx.x * blockDim.x + threadIdx.x;
    if (e >= ne) return;
    unsigned r = (unsigned)__ldg(&rows[e]);
    if (r >= NTOT) return;
    int c = __ldg(&cols[e]);
    float v = __ldg(&vals[e]);
    int p = atomicAdd(&g_pos[r], 1);
    if (p < MAXE) g_cva[p] = make_int2(c, __float_as_int(v));
}

// ---------------------------------------------------------------------------
// CSR SpMM: one 16-lane group per row, register accumulate, single store.
// LAYER 0: src = (user_emb|item_emb) direct, dst = X1
// LAYER 1: X1 -> X2
// LAYER 2: X2 -> X3, only over compacted g_rowlist (<= g_nrows rows)
// ---------------------------------------------------------------------------
template <int LAYER>
__global__ void __launch_bounds__(256)
spmm_csr_kernel(const float4* __restrict__ ue,
                const float4* __restrict__ ie) {
    int gid = blockIdx.x * blockDim.x + threadIdx.x;
    int g = gid >> 4;
    int l = gid & 15;

    int r;
    if (LAYER == 2) {
        if (g >= g_nrows) return;
        r = g_rowlist[g];
    } else {
        if (g >= NTOT) return;
        r = g;
    }

    int beg = __ldg(&g_off[r]);
    int end = __ldg(&g_off[r + 1]);

    const float4* __restrict__ src = (LAYER == 1) ? g_X1 : g_X2;  // unused L0
    float4 acc = make_float4(0.f, 0.f, 0.f, 0.f);

    int j = beg;
    for (; j + 1 < end; j += 2) {       // issue both gathers before consuming
        int2 ca = __ldg(&g_cva[j]);
        int2 cb = __ldg(&g_cva[j + 1]);
        float4 xa, xb;
        if (LAYER == 0) {
            xa = (ca.x < NUM_USERS) ? __ldg(&ue[ca.x * D4 + l])
                                    : __ldg(&ie[(ca.x - NUM_USERS) * D4 + l]);
            xb = (cb.x < NUM_USERS) ? __ldg(&ue[cb.x * D4 + l])
                                    : __ldg(&ie[(cb.x - NUM_USERS) * D4 + l]);
        } else {
            xa = __ldg(&src[ca.x * D4 + l]);
            xb = __ldg(&src[cb.x * D4 + l]);
        }
        float va = __int_as_float(ca.y), vb = __int_as_float(cb.y);
        acc.x += va * xa.x + vb * xb.x;
        acc.y += va * xa.y + vb * xb.y;
        acc.z += va * xa.z + vb * xb.z;
        acc.w += va * xa.w + vb * xb.w;
    }
    if (j < end) {
        int2 ca = __ldg(&g_cva[j]);
        float4 xa;
        if (LAYER == 0) {
            xa = (ca.x < NUM_USERS) ? __ldg(&ue[ca.x * D4 + l])
                                    : __ldg(&ie[(ca.x - NUM_USERS) * D4 + l]);
        } else {
            xa = __ldg(&src[ca.x * D4 + l]);
        }
        float va = __int_as_float(ca.y);
        acc.x += va * xa.x; acc.y += va * xa.y;
        acc.z += va * xa.z; acc.w += va * xa.w;
    }

    float4* __restrict__ dst = (LAYER == 0) ? g_X1 : (LAYER == 1) ? g_X2 : g_X3;
    dst[r * D4 + l] = acc;
}

// ---------------------------------------------------------------------------
// Readout: out[b] = dot((X1+X2+X3)[u], (X1+X2+X3)[i+NU]) / 9
// ---------------------------------------------------------------------------
__global__ void dot_kernel(const int* __restrict__ uid,
                           const int* __restrict__ iid,
                           float* __restrict__ out) {
    int gid = blockIdx.x * blockDim.x + threadIdx.x;
    int b = gid >> 4;
    int l = gid & 15;
    if (b >= BATCH) return;

    unsigned ur = (unsigned)__ldg(&uid[b]);
    unsigned ir = (unsigned)__ldg(&iid[b]) + NUM_USERS;
    float d = 0.f;

    if (ur < NTOT && ir < NTOT) {
        int uo = (int)ur * D4 + l;
        int io = (int)ir * D4 + l;
        float4 a1 = g_X1[uo], a2 = g_X2[uo], a3 = g_X3[uo];
        float4 b1 = g_X1[io], b2 = g_X2[io], b3 = g_X3[io];
        float fux = a1.x + a2.x + a3.x, fuy = a1.y + a2.y + a3.y;
        float fuz = a1.z + a2.z + a3.z, fuw = a1.w + a2.w + a3.w;
        float fix = b1.x + b2.x + b3.x, fiy = b1.y + b2.y + b3.y;
        float fiz = b1.z + b2.z + b3.z, fiw = b1.w + b2.w + b3.w;
        d = fux * fix + fuy * fiy + fuz * fiz + fuw * fiw;
    }

    #pragma unroll
    for (int off = 8; off > 0; off >>= 1)
        d += __shfl_down_sync(0xffffffffu, d, off, 16);

    if (l == 0) out[b] = d * (1.0f / 9.0f);
}

// ---------------------------------------------------------------------------
extern "C" void kernel_launch(void* const* d_in, const int* in_sizes, int n_in,
                              void* d_out, int out_size) {
    const float4* user_emb = (const float4*)d_in[0];   // [100000,64] f32
    const float4* item_emb = (const float4*)d_in[1];   // [50000,64]  f32
    const float*  vals     = (const float*) d_in[2];   // [2E] f32
    const int*    rows     = (const int*)   d_in[3];   // [2E] i32
    const int*    cols     = (const int*)   d_in[4];   // [2E] i32
    const int*    uid      = (const int*)   d_in[5];   // [4096] i32
    const int*    iid      = (const int*)   d_in[6];   // [4096] i32
    float*        out      = (float*)d_out;            // [4096] f32

    const int ne = in_sizes[2];

    // build state + flagged-row compaction
    zero_kernel<<<(NTOT + 255) / 256, 256>>>();
    mark_kernel<<<(BATCH + 255) / 256, 256>>>(uid, iid);

    // CSR build (counting sort, parallel scan)
    int eblocks = (ne + 255) / 256;
    degree_kernel<<<eblocks, 256>>>(rows, ne);
    scan_reduce_kernel<<<NBLK, SCAN_B>>>();
    scan_partials_kernel<<<1, 1024>>>();
    scan_final_kernel<<<NBLK, SCAN_B>>>();
    scatter_kernel<<<eblocks, 256>>>(vals, rows, cols, ne);

    // 3 propagation layers (layer 3 over compacted row list only)
    {
        int t_dense = NTOT * D4;
        spmm_csr_kernel<0><<<(t_dense + 255) / 256, 256>>>(user_emb, item_emb);
        spmm_csr_kernel<1><<<(t_dense + 255) / 256, 256>>>(user_emb, item_emb);
        int t_sparse = MAXROWS * 16;
        spmm_csr_kernel<2><<<(t_sparse + 255) / 256, 256>>>(user_emb, item_emb);
    }

    dot_kernel<<<(BATCH * 16 + 255) / 256, 256>>>(uid, iid, out);
}